// round 7
// baseline (speedup 1.0000x reference)
#include <cuda_runtime.h>
#include <math.h>

// Problem constants (fixed by the dataset)
#define H   128
#define OO  20
#define KI  700
#define BB  256
#define TT  250
#define MTOT (BB * TT)   // 64000

// Scratch for the hoisted input projection: xin[(b*T + t)][h]
__device__ float g_xin[(size_t)MTOT * H];

// ---------------------------------------------------------------------------
// f32x2 packed helpers (sm_103a). fma.rn.f32x2 = two independent rn fp32 FMAs
// in one fma-pipe instruction -> bitwise identical to two fmaf.
// ---------------------------------------------------------------------------
typedef unsigned long long ull;

__device__ __forceinline__ ull pk2(float lo, float hi) {
    ull r;
    asm("mov.b64 %0, {%1, %2};" : "=l"(r) : "f"(lo), "f"(hi));
    return r;
}
__device__ __forceinline__ void upk2(float& lo, float& hi, ull v) {
    asm("mov.b64 {%0, %1}, %2;" : "=f"(lo), "=f"(hi) : "l"(v));
}
__device__ __forceinline__ void ffma2(ull& acc, ull a, ull b) {
    asm("fma.rn.f32x2 %0, %1, %2, %0;" : "+l"(acc) : "l"(a), "l"(b));
}

// ---------------------------------------------------------------------------
// Bit-exact transcription of XLA CPU's vectorized expf (Cephes/Eigen pexp).
// ---------------------------------------------------------------------------
__device__ __forceinline__ float xla_expf(float xin_) {
    const float exp_hi = 88.3762626647950f;
    const float exp_lo = -88.3762626647949f;
    const float LOG2EF = 1.44269504088896341f;
    const float C1 = 0.693359375f;
    const float C2 = -2.12194440e-4f;
    const float p0 = 1.9875691500E-4f;
    const float p1 = 1.3981999507E-3f;
    const float p2 = 8.3334519073E-3f;
    const float p3 = 4.1665795894E-2f;
    const float p4 = 1.6666665459E-1f;
    const float p5 = 5.0000001201E-1f;

    float x = fminf(fmaxf(xin_, exp_lo), exp_hi);
    float fx = floorf(__fadd_rn(__fmul_rn(x, LOG2EF), 0.5f));
    float tmp = __fmul_rn(C1, fx);
    float z   = __fmul_rn(C2, fx);
    float xx  = __fsub_rn(x, tmp);
    xx = __fsub_rn(xx, z);
    z = __fmul_rn(xx, xx);
    float y = __fadd_rn(__fmul_rn(xx, p0), p1);
    y = __fadd_rn(__fmul_rn(y, xx), p2);
    y = __fadd_rn(__fmul_rn(y, xx), p3);
    y = __fadd_rn(__fmul_rn(y, xx), p4);
    y = __fadd_rn(__fmul_rn(y, xx), p5);
    y = __fadd_rn(__fmul_rn(y, z), xx);
    y = __fadd_rn(1.0f, y);
    int n = (int)fx;
    float p2n = __int_as_float((n + 127) << 23);
    float r = __fmul_rn(y, p2n);
    return fmaxf(r, xin_);
}

// ---------------------------------------------------------------------------
// Phase 1: xin = x @ w_ih1 + b_ih1   (M=64000, K=700, N=128, strict fp32)
// 512 threads/block, 128x128 tile, 4x8 micro-tile -> ~16 warps/SM occupancy.
// Ascending-k FMA chain per output (bit-identical), packed fma.rn.f32x2.
// ---------------------------------------------------------------------------
#define BM  128
#define BN  128
#define BKK 16
#define NT  44          // ceil(700/16); tail zero-padded (adds exact +0)

__global__ __launch_bounds__(512, 1)
void gemm_xin_kernel(const float* __restrict__ x,
                     const float* __restrict__ w,
                     const float* __restrict__ bias)
{
    __shared__ float As[BKK][BM + 4];
    __shared__ float Bs[BKK][BN];

    const int tid     = threadIdx.x;
    const int block_m = blockIdx.x * BM;
    const int tn      = tid & 15;     // 0..15 -> 8 cols each
    const int tm      = tid >> 4;     // 0..31 -> 4 rows each

    const int ka = tid & 15, ra = tid >> 4;     // A loader: col(k), row-base (0..31)
    const int nb = tid & 127, rbk = tid >> 7;   // B loader: col(n), row-base (0..3)

    // packed accumulators: acc2[i][jp] = (col 2*jp, col 2*jp+1) of row i
    ull acc2[4][4];
#pragma unroll
    for (int i = 0; i < 4; i++)
#pragma unroll
        for (int j = 0; j < 4; j++) acc2[i][j] = 0ull;

    float pa[4], pb[4];

    // prefetch tile 0
#pragma unroll
    for (int p = 0; p < 4; p++) {
        int kk = ka;
        int row = block_m + ra + p * 32;
        pa[p] = (kk < KI) ? x[(size_t)row * KI + kk] : 0.f;
    }
#pragma unroll
    for (int p = 0; p < 4; p++) {
        int kk = rbk + p * 4;
        pb[p] = (kk < KI) ? w[(size_t)kk * H + nb] : 0.f;
    }
#pragma unroll
    for (int p = 0; p < 4; p++) As[ka][ra + p * 32] = pa[p];
#pragma unroll
    for (int p = 0; p < 4; p++) Bs[rbk + p * 4][nb] = pb[p];
    __syncthreads();

    for (int it = 0; it < NT; it++) {
        // prefetch next tile into registers (overlaps with compute)
        if (it + 1 < NT) {
            int k0n = (it + 1) * BKK;
#pragma unroll
            for (int p = 0; p < 4; p++) {
                int kk = k0n + ka;
                int row = block_m + ra + p * 32;
                pa[p] = (kk < KI) ? x[(size_t)row * KI + kk] : 0.f;
            }
#pragma unroll
            for (int p = 0; p < 4; p++) {
                int kk = k0n + rbk + p * 4;
                pb[p] = (kk < KI) ? w[(size_t)kk * H + nb] : 0.f;
            }
        }

        // compute on current smem tile: ascending k, packed FMA
#pragma unroll
        for (int k = 0; k < BKK; k++) {
            float4 a4 = *(const float4*)&As[k][tm * 4];       // half-warp broadcast
            const float4* bp = (const float4*)&Bs[k][tn * 8];
            float4 b0 = bp[0], b1 = bp[1];
            ull bp0 = pk2(b0.x, b0.y);
            ull bp1 = pk2(b0.z, b0.w);
            ull bp2 = pk2(b1.x, b1.y);
            ull bp3 = pk2(b1.z, b1.w);
            float av[4];
            av[0]=a4.x; av[1]=a4.y; av[2]=a4.z; av[3]=a4.w;
#pragma unroll
            for (int i = 0; i < 4; i++) {
                ull apk = pk2(av[i], av[i]);
                ffma2(acc2[i][0], apk, bp0);
                ffma2(acc2[i][1], apk, bp1);
                ffma2(acc2[i][2], apk, bp2);
                ffma2(acc2[i][3], apk, bp3);
            }
        }
        __syncthreads();
        if (it + 1 < NT) {
#pragma unroll
            for (int p = 0; p < 4; p++) As[ka][ra + p * 32] = pa[p];
#pragma unroll
            for (int p = 0; p < 4; p++) Bs[rbk + p * 4][nb] = pb[p];
        }
        __syncthreads();
    }

#pragma unroll
    for (int i = 0; i < 4; i++) {
        int row = block_m + tm * 4 + i;
#pragma unroll
        for (int jp = 0; jp < 4; jp++) {
            float lo, hi;
            upk2(lo, hi, acc2[i][jp]);
            int col = tn * 8 + 2 * jp;
            g_xin[(size_t)row * H + col]     = __fadd_rn(lo, bias[col]);
            g_xin[(size_t)row * H + col + 1] = __fadd_rn(hi, bias[col + 1]);
        }
    }
}

// ---------------------------------------------------------------------------
// Spike-vector dot from SMEM weights, ascending h'. Two bitwise-identical
// paths (dense fmaf sweep vs sparse add chain), chosen by popcount.
// ---------------------------------------------------------------------------
__device__ __forceinline__
float dot_spikes(const float* __restrict__ wcol,
                 const float* __restrict__ sflv,
                 const unsigned* __restrict__ mw)
{
    unsigned m0 = mw[0], m1 = mw[1], m2 = mw[2], m3 = mw[3];
    int cnt = __popc(m0) + __popc(m1) + __popc(m2) + __popc(m3);
    float acc = 0.f;
    if (cnt >= 48) {
        const float4* s4 = (const float4*)sflv;
#pragma unroll
        for (int c = 0; c < 32; c++) {
            float4 s = s4[c];
            acc = fmaf(s.x, wcol[(4 * c + 0) * H], acc);
            acc = fmaf(s.y, wcol[(4 * c + 1) * H], acc);
            acc = fmaf(s.z, wcol[(4 * c + 2) * H], acc);
            acc = fmaf(s.w, wcol[(4 * c + 3) * H], acc);
        }
    } else if (cnt) {
        unsigned mm[4] = {m0, m1, m2, m3};
#pragma unroll
        for (int w4 = 0; w4 < 4; w4++) {
            unsigned m = mm[w4];
            if (!m) continue;
            const float* base = wcol + w4 * 32 * H;
            while (m) {
                int bit = __ffs(m) - 1;
                m &= m - 1;
                acc = __fadd_rn(acc, base[bit * H]);
            }
        }
    }
    return acc;
}

// ---------------------------------------------------------------------------
// Phase 2: sequential scan over T. One 128-thread group per batch element,
// 2 groups per block. W11 column register-resident per thread (d1 needs no
// shared-memory crossbar); W12/W22 from SMEM. Strict rn arithmetic,
// XLA-exact exp. SMEM layout (floats):
//   [0)      w12s  H*H
//   [16384)  w22s  H*H
//   [32768)  wos   H*OO (=2560)
//   [35328)  sfl   [2grp][2layer][2buf][H] = 1024
//   [36352)  msk   32 u32
//   [36384)  sfm   [2grp][32]
// total 36448 floats = 145792 bytes
// ---------------------------------------------------------------------------
#define SCAN_SMEM_BYTES (36448 * 4)

__global__ __launch_bounds__(256, 1)
void snn_scan_kernel(const float* __restrict__ mask,
                     const float* __restrict__ w11g, const float* __restrict__ b11g,
                     const float* __restrict__ w12g, const float* __restrict__ b12g,
                     const float* __restrict__ w22g, const float* __restrict__ b22g,
                     const float* __restrict__ wog,  const float* __restrict__ bog,
                     const float* __restrict__ tau_adp1, const float* __restrict__ tau_adp2,
                     const float* __restrict__ tau_m1,   const float* __restrict__ tau_m2,
                     const float* __restrict__ tau_mo,
                     const float* __restrict__ h1m0, const float* __restrict__ h2m0,
                     const float* __restrict__ om0,
                     float* __restrict__ out_acc,
                     float* __restrict__ out_s1,
                     float* __restrict__ out_s2)
{
    extern __shared__ float smf[];
    float*    w12s = smf;
    float*    w22s = smf + 16384;
    float*    wos  = smf + 32768;
    float*    sflb = smf + 35328;
    unsigned* mskb = (unsigned*)(smf + 36352);
    float*    sfm  = smf + 36384;

    const int tid  = threadIdx.x;
    const int g    = tid & (H - 1);
    const int grp  = tid >> 7;
    const int b    = blockIdx.x * 2 + grp;
    const int lane = tid & 31;
    const int wig  = g >> 5;

    for (int i = tid; i < H * H; i += blockDim.x) {
        w12s[i] = w12g[i];
        w22s[i] = __fmul_rn(w22g[i], mask[H * H + i]);
    }
    for (int i = tid; i < H * OO; i += blockDim.x) wos[i] = wog[i];
    for (int i = tid; i < 2 * 2 * 2 * H; i += blockDim.x) sflb[i] = 0.f;
    if (tid < 32) mskb[tid] = 0u;
    if (tid < 64) sfm[tid] = 0.f;
    __syncthreads();

    // W11 column g register-resident (fully-unrolled indexing only)
    float w11r[H];
#pragma unroll
    for (int hp = 0; hp < H; hp++)
        w11r[hp] = __fmul_rn(w11g[hp * H + g], mask[hp * H + g]);

    // Decay constants with XLA-exact exp(-1/tau)
    const float a1    = xla_expf(__fdiv_rn(-1.f, tau_m1[g]));
    const float r1    = xla_expf(__fdiv_rn(-1.f, tau_adp1[g]));
    const float a2    = xla_expf(__fdiv_rn(-1.f, tau_m2[g]));
    const float r2    = xla_expf(__fdiv_rn(-1.f, tau_adp2[g]));
    const float om_a1 = __fsub_rn(1.f, a1);
    const float om_r1 = __fsub_rn(1.f, r1);
    const float om_a2 = __fsub_rn(1.f, a2);
    const float om_r2 = __fsub_rn(1.f, r2);
    const float bi1 = b11g[g];
    const float b12 = b12g[g];
    const float b22 = b22g[g];

    float h1m = h1m0[b * H + g];
    float h2m = h2m0[b * H + g];
    float bb1 = 0.01f, bb2 = 0.01f;
    float spk1 = 0.f, spk2 = 0.f;
    float s1c = 0.f, s2c = 0.f;

    float om = 0.f, ao = 0.f, om_ao = 0.f, bo = 0.f, accv = 0.f;
    if (g < OO) {
        om    = om0[b * OO + g];
        ao    = xla_expf(__fdiv_rn(-1.f, tau_mo[g]));
        om_ao = __fsub_rn(1.f, ao);
        bo    = bog[g];
    }

    float*    sfl1 = sflb + grp * (2 * 2 * H);
    float*    sfl2 = sfl1 + 2 * H;
    unsigned* mk1  = mskb + grp * 16;
    unsigned* mk2  = mk1 + 8;
    float*    sfmg = sfm + grp * 32;

    const float* xrow = g_xin + (size_t)b * TT * H + g;

    float xt_cur = xrow[0];

#pragma unroll 1
    for (int t = 0; t < TT; t++) {
        const int p = t & 1, q = p ^ 1;
        // prefetch next timestep's input (latency hidden behind dots)
        float xt_next = (t + 1 < TT) ? xrow[(size_t)(t + 1) * H] : 0.f;

        // ---- layer 1 (adaptive LIF): d1 from REGISTER weights ----
        // Ascending predicated-add chain == sparse chain == dense fmaf chain.
        float d1 = 0.f;
        {
            unsigned mw0 = mk1[p * 4 + 0], mw1 = mk1[p * 4 + 1];
            unsigned mw2 = mk1[p * 4 + 2], mw3 = mk1[p * 4 + 3];
#pragma unroll
            for (int hp2 = 0; hp2 < 32; hp2++)
                if (mw0 & (1u << hp2)) d1 = __fadd_rn(d1, w11r[hp2]);
#pragma unroll
            for (int hp2 = 0; hp2 < 32; hp2++)
                if (mw1 & (1u << hp2)) d1 = __fadd_rn(d1, w11r[32 + hp2]);
#pragma unroll
            for (int hp2 = 0; hp2 < 32; hp2++)
                if (mw2 & (1u << hp2)) d1 = __fadd_rn(d1, w11r[64 + hp2]);
#pragma unroll
            for (int hp2 = 0; hp2 < 32; hp2++)
                if (mw3 & (1u << hp2)) d1 = __fadd_rn(d1, w11r[96 + hp2]);
        }
        float i1 = __fadd_rn(__fadd_rn(xt_cur, d1), bi1);
        bb1 = __fadd_rn(__fmul_rn(r1, bb1), __fmul_rn(om_r1, spk1));
        float B1 = __fadd_rn(0.01f, __fmul_rn(1.8f, bb1));
        h1m = __fsub_rn(__fadd_rn(__fmul_rn(h1m, a1), __fmul_rn(om_a1, i1)),
                        __fmul_rn(B1, spk1));
        float ns1 = (__fsub_rn(h1m, B1) > 0.f) ? 1.f : 0.f;
        s1c = __fadd_rn(s1c, ns1);
        spk1 = ns1;
        unsigned bal = __ballot_sync(0xffffffffu, ns1 != 0.f);
        sfl1[q * H + g] = ns1;
        if (lane == 0) mk1[q * 4 + wig] = bal;
        __syncthreads();

        // ---- layer 2 (adaptive LIF) ----
        float d12 = dot_spikes(w12s + g, sfl1 + q * H, mk1 + q * 4);
        float d22 = dot_spikes(w22s + g, sfl2 + p * H, mk2 + p * 4);
        float i2 = __fadd_rn(__fadd_rn(__fadd_rn(d12, b12), d22), b22);
        bb2 = __fadd_rn(__fmul_rn(r2, bb2), __fmul_rn(om_r2, spk2));
        float B2 = __fadd_rn(0.01f, __fmul_rn(1.8f, bb2));
        h2m = __fsub_rn(__fadd_rn(__fmul_rn(h2m, a2), __fmul_rn(om_a2, i2)),
                        __fmul_rn(B2, spk2));
        float ns2 = (__fsub_rn(h2m, B2) > 0.f) ? 1.f : 0.f;
        s2c = __fadd_rn(s2c, ns2);
        spk2 = ns2;
        bal = __ballot_sync(0xffffffffu, ns2 != 0.f);
        sfl2[q * H + g] = ns2;
        if (lane == 0) mk2[q * 4 + wig] = bal;
        __syncthreads();

        // ---- leaky readout + softmax accumulation (first warp of group) ----
        if (g < 32) {
            if (g < OO) {
                float io = 0.f;
#pragma unroll
                for (int w4 = 0; w4 < 4; w4++) {
                    unsigned m = mk2[q * 4 + w4];
                    const float* base = wos + w4 * 32 * OO + g;
                    while (m) {
                        int bit = __ffs(m) - 1;
                        m &= m - 1;
                        io = __fadd_rn(io, base[bit * OO]);
                    }
                }
                io = __fadd_rn(io, bo);
                om = __fadd_rn(__fmul_rn(om, ao), __fmul_rn(om_ao, io));
            }
            float v = (g < OO) ? om : -1e30f;
#pragma unroll
            for (int off = 16; off; off >>= 1)
                v = fmaxf(v, __shfl_xor_sync(0xffffffffu, v, off));
            float e = (g < OO) ? xla_expf(__fsub_rn(om, v)) : 0.f;
            sfmg[g] = e;
            __syncwarp(0xffffffffu);
            float ssum = 0.f;
#pragma unroll
            for (int j = 0; j < OO; j++)
                ssum = __fadd_rn(ssum, sfmg[j]);
            __syncwarp(0xffffffffu);
            if (t > 10 && g < OO) accv = __fadd_rn(accv, __fdiv_rn(e, ssum));
        }
        xt_cur = xt_next;
    }

    if (g < OO) out_acc[b * OO + g] = accv;
    out_s1[b * H + g] = __fdiv_rn(s1c, 250.f);
    out_s2[b * H + g] = __fdiv_rn(s2c, 250.f);
}

// ---------------------------------------------------------------------------
// A_norm = sum |w_h1h1 * mask0| + sum |w_h2h2 * mask1|
// ---------------------------------------------------------------------------
__global__ void anorm_kernel(const float* __restrict__ w11g,
                             const float* __restrict__ w22g,
                             const float* __restrict__ mask,
                             float* __restrict__ out)
{
    __shared__ float red[256];
    float s1 = 0.f, s2 = 0.f;
    for (int i = threadIdx.x; i < H * H; i += 256) {
        s1 = __fadd_rn(s1, fabsf(__fmul_rn(w11g[i], mask[i])));
        s2 = __fadd_rn(s2, fabsf(__fmul_rn(w22g[i], mask[H * H + i])));
    }
    red[threadIdx.x] = __fadd_rn(s1, s2);
    __syncthreads();
    for (int st = 128; st; st >>= 1) {
        if (threadIdx.x < st)
            red[threadIdx.x] = __fadd_rn(red[threadIdx.x], red[threadIdx.x + st]);
        __syncthreads();
    }
    if (threadIdx.x == 0) out[0] = red[0];
}

// ---------------------------------------------------------------------------
extern "C" void kernel_launch(void* const* d_in, const int* in_sizes, int n_in,
                              void* d_out, int out_size)
{
    const float* x          = (const float*)d_in[0];
    const float* mask       = (const float*)d_in[1];
    const float* w_ih1      = (const float*)d_in[2];
    const float* b_ih1      = (const float*)d_in[3];
    const float* w_h1h1     = (const float*)d_in[4];
    const float* b_h1h1     = (const float*)d_in[5];
    const float* w_h1h2     = (const float*)d_in[6];
    const float* b_h1h2     = (const float*)d_in[7];
    const float* w_h2h2     = (const float*)d_in[8];
    const float* b_h2h2     = (const float*)d_in[9];
    const float* w_h2o      = (const float*)d_in[10];
    const float* b_h2o      = (const float*)d_in[11];
    const float* tau_adp_h1 = (const float*)d_in[12];
    const float* tau_adp_h2 = (const float*)d_in[13];
    const float* tau_m_h1   = (const float*)d_in[14];
    const float* tau_m_h2   = (const float*)d_in[15];
    const float* tau_m_o    = (const float*)d_in[16];
    const float* h1m0       = (const float*)d_in[17];
    const float* h2m0       = (const float*)d_in[18];
    const float* om0        = (const float*)d_in[19];

    float* out = (float*)d_out;
    float* out_acc = out;
    float* out_s1  = out + BB * OO;
    float* out_s2  = out + BB * OO + BB * H;
    float* out_an  = out + BB * OO + 2 * BB * H;

    cudaFuncSetAttribute(snn_scan_kernel,
                         cudaFuncAttributeMaxDynamicSharedMemorySize,
                         SCAN_SMEM_BYTES);

    gemm_xin_kernel<<<MTOT / BM, 512>>>(x, w_ih1, b_ih1);

    snn_scan_kernel<<<BB / 2, 256, SCAN_SMEM_BYTES>>>(
        mask,
        w_h1h1, b_h1h1, w_h1h2, b_h1h2, w_h2h2, b_h2h2, w_h2o, b_h2o,
        tau_adp_h1, tau_adp_h2, tau_m_h1, tau_m_h2, tau_m_o,
        h1m0, h2m0, om0,
        out_acc, out_s1, out_s2);

    anorm_kernel<<<1, 256>>>(w_h1h1, w_h2h2, mask, out_an);
}

// round 10
// speedup vs baseline: 1.2898x; 1.2898x over previous
#include <cuda_runtime.h>
#include <stdint.h>
#include <math.h>

// Problem constants (fixed by the dataset)
#define H   128
#define OO  20
#define KI  700
#define BB  256
#define TT  250
#define MTOT (BB * TT)   // 64000

// Scratch for the hoisted input projection: xin[(b*T + t)][h]
__device__ float g_xin[(size_t)MTOT * H];

// ---------------------------------------------------------------------------
// f32x2 packed helpers (sm_103a). fma.rn.f32x2 = two independent rn fp32 FMAs
// in one fma-pipe instruction -> bitwise identical to two fmaf.
// ---------------------------------------------------------------------------
typedef unsigned long long ull;

__device__ __forceinline__ ull pk2(float lo, float hi) {
    ull r;
    asm("mov.b64 %0, {%1, %2};" : "=l"(r) : "f"(lo), "f"(hi));
    return r;
}
__device__ __forceinline__ void upk2(float& lo, float& hi, ull v) {
    asm("mov.b64 {%0, %1}, %2;" : "=f"(lo), "=f"(hi) : "l"(v));
}
__device__ __forceinline__ void ffma2(ull& acc, ull a, ull b) {
    asm("fma.rn.f32x2 %0, %1, %2, %0;" : "+l"(acc) : "l"(a), "l"(b));
}

// cp.async wrappers
__device__ __forceinline__ void cpa4(unsigned int dst, const void* src) {
    asm volatile("cp.async.ca.shared.global [%0], [%1], 4;" :: "r"(dst), "l"(src));
}
__device__ __forceinline__ void cpa16(unsigned int dst, const void* src) {
    asm volatile("cp.async.cg.shared.global [%0], [%1], 16;" :: "r"(dst), "l"(src));
}
__device__ __forceinline__ void cpa_commit() {
    asm volatile("cp.async.commit_group;");
}
__device__ __forceinline__ void cpa_wait_all() {
    asm volatile("cp.async.wait_group 0;");
}

// ---------------------------------------------------------------------------
// Bit-exact transcription of XLA CPU's vectorized expf (Cephes/Eigen pexp).
// ---------------------------------------------------------------------------
__device__ __forceinline__ float xla_expf(float xin_) {
    const float exp_hi = 88.3762626647950f;
    const float exp_lo = -88.3762626647949f;
    const float LOG2EF = 1.44269504088896341f;
    const float C1 = 0.693359375f;
    const float C2 = -2.12194440e-4f;
    const float p0 = 1.9875691500E-4f;
    const float p1 = 1.3981999507E-3f;
    const float p2 = 8.3334519073E-3f;
    const float p3 = 4.1665795894E-2f;
    const float p4 = 1.6666665459E-1f;
    const float p5 = 5.0000001201E-1f;

    float x = fminf(fmaxf(xin_, exp_lo), exp_hi);
    float fx = floorf(__fadd_rn(__fmul_rn(x, LOG2EF), 0.5f));
    float tmp = __fmul_rn(C1, fx);
    float z   = __fmul_rn(C2, fx);
    float xx  = __fsub_rn(x, tmp);
    xx = __fsub_rn(xx, z);
    z = __fmul_rn(xx, xx);
    float y = __fadd_rn(__fmul_rn(xx, p0), p1);
    y = __fadd_rn(__fmul_rn(y, xx), p2);
    y = __fadd_rn(__fmul_rn(y, xx), p3);
    y = __fadd_rn(__fmul_rn(y, xx), p4);
    y = __fadd_rn(__fmul_rn(y, xx), p5);
    y = __fadd_rn(__fmul_rn(y, z), xx);
    y = __fadd_rn(1.0f, y);
    int n = (int)fx;
    float p2n = __int_as_float((n + 127) << 23);
    float r = __fmul_rn(y, p2n);
    return fmaxf(r, xin_);
}

// ---------------------------------------------------------------------------
// Phase 1: xin = x @ w_ih1 + b_ih1   (M=64000, K=700, N=128, strict fp32)
// 256 threads, 128x128 tile, 8x8 micro-tile, cp.async double-buffered smem
// (one __syncthreads per tile), FFMA2, 2 blocks/SM.
// Ascending-k FMA chain per output — bit-identical to prior rounds.
// ---------------------------------------------------------------------------
#define BM  128
#define BN  128
#define BKK 16
#define NT  44          // ceil(700/16); tail zero-filled (adds exact +0)
#define ASTRIDE (BM + 4)

__global__ __launch_bounds__(256, 2)
void gemm_xin_kernel(const float* __restrict__ x,
                     const float* __restrict__ w,
                     const float* __restrict__ bias)
{
    __shared__ float As[2][BKK][ASTRIDE];
    __shared__ float Bs[2][BKK][BN];

    const int tid     = threadIdx.x;
    const int block_m = blockIdx.x * BM;
    const int tn      = tid & 15;    // 0..15 -> 8 cols each
    const int tm      = tid >> 4;    // 0..15 -> 8 rows each

    const int ka = tid & 15, ra = tid >> 4;       // A loader
    const int brow = tid >> 5, bcol4 = tid & 31;  // B loader (float4)

    ull acc2[8][4];
#pragma unroll
    for (int i = 0; i < 8; i++)
#pragma unroll
        for (int j = 0; j < 4; j++) acc2[i][j] = 0ull;

    // issue async loads of tile `it` into buffer `buf`
    auto issue_loads = [&](int it, int buf) {
        int k0 = it * BKK;
        // A: 8 scalars per thread
#pragma unroll
        for (int p = 0; p < 8; p++) {
            int kk = k0 + ka;
            int m  = ra + p * 16;
            int row = block_m + m;
            if (kk < KI) {
                unsigned int dst =
                    (unsigned int)__cvta_generic_to_shared(&As[buf][ka][m]);
                cpa4(dst, x + (size_t)row * KI + kk);
            } else {
                As[buf][ka][m] = 0.f;
            }
        }
        // B: 2 float4 per thread (rows brow and brow+8)
#pragma unroll
        for (int q = 0; q < 2; q++) {
            int r = brow + q * 8;
            int kk = k0 + r;
            if (kk < KI) {
                unsigned int dst =
                    (unsigned int)__cvta_generic_to_shared(&Bs[buf][r][bcol4 * 4]);
                cpa16(dst, w + (size_t)kk * H + bcol4 * 4);
            } else {
                *(float4*)&Bs[buf][r][bcol4 * 4] = make_float4(0.f, 0.f, 0.f, 0.f);
            }
        }
        cpa_commit();
    };

    issue_loads(0, 0);

    for (int it = 0; it < NT; it++) {
        cpa_wait_all();
        __syncthreads();
        const int cur = it & 1;
        if (it + 1 < NT) issue_loads(it + 1, cur ^ 1);

        // compute on current smem tile: ascending k, packed FMA
#pragma unroll
        for (int k = 0; k < BKK; k++) {
            const float4* ap = (const float4*)&As[cur][k][tm * 8];
            const float4* bp = (const float4*)&Bs[cur][k][tn * 8];
            float4 a0 = ap[0], a1 = ap[1];
            float4 b0 = bp[0], b1 = bp[1];
            ull bp0 = pk2(b0.x, b0.y);
            ull bp1 = pk2(b0.z, b0.w);
            ull bp2 = pk2(b1.x, b1.y);
            ull bp3 = pk2(b1.z, b1.w);
            float av[8];
            av[0]=a0.x; av[1]=a0.y; av[2]=a0.z; av[3]=a0.w;
            av[4]=a1.x; av[5]=a1.y; av[6]=a1.z; av[7]=a1.w;
#pragma unroll
            for (int i = 0; i < 8; i++) {
                ull apk = pk2(av[i], av[i]);
                ffma2(acc2[i][0], apk, bp0);
                ffma2(acc2[i][1], apk, bp1);
                ffma2(acc2[i][2], apk, bp2);
                ffma2(acc2[i][3], apk, bp3);
            }
        }
    }

#pragma unroll
    for (int i = 0; i < 8; i++) {
        int row = block_m + tm * 8 + i;
#pragma unroll
        for (int jp = 0; jp < 4; jp++) {
            float lo, hi;
            upk2(lo, hi, acc2[i][jp]);
            int col = tn * 8 + 2 * jp;
            g_xin[(size_t)row * H + col]     = __fadd_rn(lo, bias[col]);
            g_xin[(size_t)row * H + col + 1] = __fadd_rn(hi, bias[col + 1]);
        }
    }
}

// ---------------------------------------------------------------------------
// Fused dual spike-dot: two independent ascending chains (d12, d22) that
// interleave in the pipeline. Each chain bitwise identical to its standalone
// sparse/dense form (fmaf with s in {0,1} == predicated __fadd_rn).
// ---------------------------------------------------------------------------
__device__ __forceinline__
void dot_dual(const float* __restrict__ w12col, const float* __restrict__ w22col,
              const float* __restrict__ s1v, const float* __restrict__ s2v,
              const unsigned* __restrict__ m1w, const unsigned* __restrict__ m2w,
              float& d12o, float& d22o)
{
    int c1 = __popc(m1w[0]) + __popc(m1w[1]) + __popc(m1w[2]) + __popc(m1w[3]);
    int c2 = __popc(m2w[0]) + __popc(m2w[1]) + __popc(m2w[2]) + __popc(m2w[3]);
    float d12 = 0.f, d22 = 0.f;
    if (c1 + c2 >= 96) {
        const float4* s14 = (const float4*)s1v;
        const float4* s24 = (const float4*)s2v;
#pragma unroll
        for (int c = 0; c < 32; c++) {
            float4 s1 = s14[c];
            float4 s2 = s24[c];
            d12 = fmaf(s1.x, w12col[(4 * c + 0) * H], d12);
            d22 = fmaf(s2.x, w22col[(4 * c + 0) * H], d22);
            d12 = fmaf(s1.y, w12col[(4 * c + 1) * H], d12);
            d22 = fmaf(s2.y, w22col[(4 * c + 1) * H], d22);
            d12 = fmaf(s1.z, w12col[(4 * c + 2) * H], d12);
            d22 = fmaf(s2.z, w22col[(4 * c + 2) * H], d22);
            d12 = fmaf(s1.w, w12col[(4 * c + 3) * H], d12);
            d22 = fmaf(s2.w, w22col[(4 * c + 3) * H], d22);
        }
    } else {
#pragma unroll
        for (int w4 = 0; w4 < 4; w4++) {
            unsigned m1 = m1w[w4], m2 = m2w[w4];
            const float* b1 = w12col + w4 * 32 * H;
            const float* b2 = w22col + w4 * 32 * H;
            while (m1 | m2) {     // interleave the two chains bit-by-bit
                if (m1) {
                    int bit = __ffs(m1) - 1;
                    m1 &= m1 - 1;
                    d12 = __fadd_rn(d12, b1[bit * H]);
                }
                if (m2) {
                    int bit = __ffs(m2) - 1;
                    m2 &= m2 - 1;
                    d22 = __fadd_rn(d22, b2[bit * H]);
                }
            }
        }
    }
    d12o = d12;
    d22o = d22;
}

// ---------------------------------------------------------------------------
// Phase 2: sequential scan over T. One 128-thread group per batch element,
// 2 groups per block, per-group NAMED barriers (groups fully decoupled).
// W11 column register-resident; W12/W22 from SMEM. Strict rn arithmetic,
// XLA-exact exp. SMEM layout (floats):
//   [0)      w12s  H*H
//   [16384)  w22s  H*H
//   [32768)  wos   H*OO (=2560)
//   [35328)  sfl   [2grp][2layer][2buf][H] = 1024
//   [36352)  msk   32 u32
//   [36384)  sfm   [2grp][32]
// ---------------------------------------------------------------------------
#define SCAN_SMEM_BYTES (36448 * 4)

__global__ __launch_bounds__(256, 1)
void snn_scan_kernel(const float* __restrict__ mask,
                     const float* __restrict__ w11g, const float* __restrict__ b11g,
                     const float* __restrict__ w12g, const float* __restrict__ b12g,
                     const float* __restrict__ w22g, const float* __restrict__ b22g,
                     const float* __restrict__ wog,  const float* __restrict__ bog,
                     const float* __restrict__ tau_adp1, const float* __restrict__ tau_adp2,
                     const float* __restrict__ tau_m1,   const float* __restrict__ tau_m2,
                     const float* __restrict__ tau_mo,
                     const float* __restrict__ h1m0, const float* __restrict__ h2m0,
                     const float* __restrict__ om0,
                     float* __restrict__ out_acc,
                     float* __restrict__ out_s1,
                     float* __restrict__ out_s2)
{
    extern __shared__ float smf[];
    float*    w12s = smf;
    float*    w22s = smf + 16384;
    float*    wos  = smf + 32768;
    float*    sflb = smf + 35328;
    unsigned* mskb = (unsigned*)(smf + 36352);
    float*    sfm  = smf + 36384;

    const int tid  = threadIdx.x;
    const int g    = tid & (H - 1);
    const int grp  = tid >> 7;
    const int b    = blockIdx.x * 2 + grp;
    const int lane = tid & 31;
    const int wig  = g >> 5;
    const int barid = grp + 1;          // named barrier per group

    for (int i = tid; i < H * H; i += blockDim.x) {
        w12s[i] = w12g[i];
        w22s[i] = __fmul_rn(w22g[i], mask[H * H + i]);
    }
    for (int i = tid; i < H * OO; i += blockDim.x) wos[i] = wog[i];
    for (int i = tid; i < 2 * 2 * 2 * H; i += blockDim.x) sflb[i] = 0.f;
    if (tid < 32) mskb[tid] = 0u;
    if (tid < 64) sfm[tid] = 0.f;
    __syncthreads();

    // W11 column g register-resident
    float w11r[H];
#pragma unroll
    for (int hp = 0; hp < H; hp++)
        w11r[hp] = __fmul_rn(w11g[hp * H + g], mask[hp * H + g]);

    const float a1    = xla_expf(__fdiv_rn(-1.f, tau_m1[g]));
    const float r1    = xla_expf(__fdiv_rn(-1.f, tau_adp1[g]));
    const float a2    = xla_expf(__fdiv_rn(-1.f, tau_m2[g]));
    const float r2    = xla_expf(__fdiv_rn(-1.f, tau_adp2[g]));
    const float om_a1 = __fsub_rn(1.f, a1);
    const float om_r1 = __fsub_rn(1.f, r1);
    const float om_a2 = __fsub_rn(1.f, a2);
    const float om_r2 = __fsub_rn(1.f, r2);
    const float bi1 = b11g[g];
    const float b12 = b12g[g];
    const float b22 = b22g[g];

    float h1m = h1m0[b * H + g];
    float h2m = h2m0[b * H + g];
    float bb1 = 0.01f, bb2 = 0.01f;
    float spk1 = 0.f, spk2 = 0.f;
    float s1c = 0.f, s2c = 0.f;

    float om = 0.f, ao = 0.f, om_ao = 0.f, bo = 0.f, accv = 0.f;
    if (g < OO) {
        om    = om0[b * OO + g];
        ao    = xla_expf(__fdiv_rn(-1.f, tau_mo[g]));
        om_ao = __fsub_rn(1.f, ao);
        bo    = bog[g];
    }

    float*    sfl1 = sflb + grp * (2 * 2 * H);
    float*    sfl2 = sfl1 + 2 * H;
    unsigned* mk1  = mskb + grp * 16;
    unsigned* mk2  = mk1 + 8;
    float*    sfmg = sfm + grp * 32;

    const float* xrow = g_xin + (size_t)b * TT * H + g;

    float xt_cur = xrow[0];

#pragma unroll 1
    for (int t = 0; t < TT; t++) {
        const int p = t & 1, q = p ^ 1;
        float xt_next = (t + 1 < TT) ? xrow[(size_t)(t + 1) * H] : 0.f;

        // ---- layer 1 (adaptive LIF): d1 from REGISTER weights ----
        float d1 = 0.f;
        {
            unsigned mw0 = mk1[p * 4 + 0], mw1 = mk1[p * 4 + 1];
            unsigned mw2 = mk1[p * 4 + 2], mw3 = mk1[p * 4 + 3];
#pragma unroll
            for (int hp2 = 0; hp2 < 32; hp2++)
                if (mw0 & (1u << hp2)) d1 = __fadd_rn(d1, w11r[hp2]);
#pragma unroll
            for (int hp2 = 0; hp2 < 32; hp2++)
                if (mw1 & (1u << hp2)) d1 = __fadd_rn(d1, w11r[32 + hp2]);
#pragma unroll
            for (int hp2 = 0; hp2 < 32; hp2++)
                if (mw2 & (1u << hp2)) d1 = __fadd_rn(d1, w11r[64 + hp2]);
#pragma unroll
            for (int hp2 = 0; hp2 < 32; hp2++)
                if (mw3 & (1u << hp2)) d1 = __fadd_rn(d1, w11r[96 + hp2]);
        }
        float i1 = __fadd_rn(__fadd_rn(xt_cur, d1), bi1);
        bb1 = __fadd_rn(__fmul_rn(r1, bb1), __fmul_rn(om_r1, spk1));
        float B1 = __fadd_rn(0.01f, __fmul_rn(1.8f, bb1));
        h1m = __fsub_rn(__fadd_rn(__fmul_rn(h1m, a1), __fmul_rn(om_a1, i1)),
                        __fmul_rn(B1, spk1));
        float ns1 = (__fsub_rn(h1m, B1) > 0.f) ? 1.f : 0.f;
        s1c = __fadd_rn(s1c, ns1);
        spk1 = ns1;
        unsigned bal = __ballot_sync(0xffffffffu, ns1 != 0.f);
        sfl1[q * H + g] = ns1;
        if (lane == 0) mk1[q * 4 + wig] = bal;
        asm volatile("bar.sync %0, %1;" :: "r"(barid), "r"(128) : "memory");

        // ---- layer 2 (adaptive LIF): fused dual dot ----
        float d12, d22;
        dot_dual(w12s + g, w22s + g, sfl1 + q * H, sfl2 + p * H,
                 mk1 + q * 4, mk2 + p * 4, d12, d22);
        float i2 = __fadd_rn(__fadd_rn(__fadd_rn(d12, b12), d22), b22);
        bb2 = __fadd_rn(__fmul_rn(r2, bb2), __fmul_rn(om_r2, spk2));
        float B2 = __fadd_rn(0.01f, __fmul_rn(1.8f, bb2));
        h2m = __fsub_rn(__fadd_rn(__fmul_rn(h2m, a2), __fmul_rn(om_a2, i2)),
                        __fmul_rn(B2, spk2));
        float ns2 = (__fsub_rn(h2m, B2) > 0.f) ? 1.f : 0.f;
        s2c = __fadd_rn(s2c, ns2);
        spk2 = ns2;
        bal = __ballot_sync(0xffffffffu, ns2 != 0.f);
        sfl2[q * H + g] = ns2;
        if (lane == 0) mk2[q * 4 + wig] = bal;
        asm volatile("bar.sync %0, %1;" :: "r"(barid), "r"(128) : "memory");

        // ---- leaky readout + softmax accumulation (first warp of group) ----
        if (g < 32) {
            if (g < OO) {
                float io = 0.f;
#pragma unroll
                for (int w4 = 0; w4 < 4; w4++) {
                    unsigned m = mk2[q * 4 + w4];
                    const float* base = wos + w4 * 32 * OO + g;
                    while (m) {
                        int bit = __ffs(m) - 1;
                        m &= m - 1;
                        io = __fadd_rn(io, base[bit * OO]);
                    }
                }
                io = __fadd_rn(io, bo);
                om = __fadd_rn(__fmul_rn(om, ao), __fmul_rn(om_ao, io));
            }
            float v = (g < OO) ? om : -1e30f;
#pragma unroll
            for (int off = 16; off; off >>= 1)
                v = fmaxf(v, __shfl_xor_sync(0xffffffffu, v, off));
            float e = (g < OO) ? xla_expf(__fsub_rn(om, v)) : 0.f;
            sfmg[g] = e;
            __syncwarp(0xffffffffu);
            float ssum = 0.f;
#pragma unroll
            for (int j = 0; j < OO; j++)
                ssum = __fadd_rn(ssum, sfmg[j]);
            __syncwarp(0xffffffffu);
            if (t > 10 && g < OO) accv = __fadd_rn(accv, __fdiv_rn(e, ssum));
        }
        xt_cur = xt_next;
    }

    if (g < OO) out_acc[b * OO + g] = accv;
    out_s1[b * H + g] = __fdiv_rn(s1c, 250.f);
    out_s2[b * H + g] = __fdiv_rn(s2c, 250.f);
}

// ---------------------------------------------------------------------------
// A_norm = sum |w_h1h1 * mask0| + sum |w_h2h2 * mask1|
// ---------------------------------------------------------------------------
__global__ void anorm_kernel(const float* __restrict__ w11g,
                             const float* __restrict__ w22g,
                             const float* __restrict__ mask,
                             float* __restrict__ out)
{
    __shared__ float red[256];
    float s1 = 0.f, s2 = 0.f;
    for (int i = threadIdx.x; i < H * H; i += 256) {
        s1 = __fadd_rn(s1, fabsf(__fmul_rn(w11g[i], mask[i])));
        s2 = __fadd_rn(s2, fabsf(__fmul_rn(w22g[i], mask[H * H + i])));
    }
    red[threadIdx.x] = __fadd_rn(s1, s2);
    __syncthreads();
    for (int st = 128; st; st >>= 1) {
        if (threadIdx.x < st)
            red[threadIdx.x] = __fadd_rn(red[threadIdx.x], red[threadIdx.x + st]);
        __syncthreads();
    }
    if (threadIdx.x == 0) out[0] = red[0];
}

// ---------------------------------------------------------------------------
extern "C" void kernel_launch(void* const* d_in, const int* in_sizes, int n_in,
                              void* d_out, int out_size)
{
    const float* x          = (const float*)d_in[0];
    const float* mask       = (const float*)d_in[1];
    const float* w_ih1      = (const float*)d_in[2];
    const float* b_ih1      = (const float*)d_in[3];
    const float* w_h1h1     = (const float*)d_in[4];
    const float* b_h1h1     = (const float*)d_in[5];
    const float* w_h1h2     = (const float*)d_in[6];
    const float* b_h1h2     = (const float*)d_in[7];
    const float* w_h2h2     = (const float*)d_in[8];
    const float* b_h2h2     = (const float*)d_in[9];
    const float* w_h2o      = (const float*)d_in[10];
    const float* b_h2o      = (const float*)d_in[11];
    const float* tau_adp_h1 = (const float*)d_in[12];
    const float* tau_adp_h2 = (const float*)d_in[13];
    const float* tau_m_h1   = (const float*)d_in[14];
    const float* tau_m_h2   = (const float*)d_in[15];
    const float* tau_m_o    = (const float*)d_in[16];
    const float* h1m0       = (const float*)d_in[17];
    const float* h2m0       = (const float*)d_in[18];
    const float* om0        = (const float*)d_in[19];

    float* out = (float*)d_out;
    float* out_acc = out;
    float* out_s1  = out + BB * OO;
    float* out_s2  = out + BB * OO + BB * H;
    float* out_an  = out + BB * OO + 2 * BB * H;

    cudaFuncSetAttribute(snn_scan_kernel,
                         cudaFuncAttributeMaxDynamicSharedMemorySize,
                         SCAN_SMEM_BYTES);

    gemm_xin_kernel<<<MTOT / BM, 256>>>(x, w_ih1, b_ih1);

    snn_scan_kernel<<<BB / 2, 256, SCAN_SMEM_BYTES>>>(
        mask,
        w_h1h1, b_h1h1, w_h1h2, b_h1h2, w_h2h2, b_h2h2, w_h2o, b_h2o,
        tau_adp_h1, tau_adp_h2, tau_m_h1, tau_m_h2, tau_m_o,
        h1m0, h2m0, om0,
        out_acc, out_s1, out_s2);

    anorm_kernel<<<1, 256>>>(w_h1h1, w_h2h2, mask, out_an);
}